// round 1
// baseline (speedup 1.0000x reference)
#include <cuda_runtime.h>
#include <math.h>

#define NATOM 50000
#define MNBR  12
#define AF    64
#define NBRF  41
#define ORIG  92
#define NCONV 3
#define NM    (NATOM*MNBR)
#define BCRY  500
#define NACRY 100
#define BN_EPS 1e-5f

// ---------------- scratch (static __device__, no allocation) ----------------
static __device__ float g_h[NATOM*AF];            // current atom features
static __device__ float g_CH[NATOM*256];          // [0:128)=h@Wc^T, [128:256)=h@Wn^T
static __device__ float g_gated[(size_t)NM*128];  // 307 MB gated pre-activation
static __device__ float g_summed[NATOM*AF];
static __device__ float g_Wpre[64*256];           // packed [Wc^T|Wn^T] (k-major)
static __device__ float g_WfT[41*128];            // Wf^T (k-major)
static __device__ float g_stats1[256];            // sum[128], sumsq[128]
static __device__ float g_stats2[128];            // sum[64], sumsq[64]
static __device__ float g_bnp1[256];              // a[128], c[128]
static __device__ float g_bnp2[128];              // a[64], c[64]
static __device__ float g_inv[NATOM];             // per-atom 1/max(norm,1e-12)
static __device__ float g_pooled[BCRY*AF];

__device__ __forceinline__ float softplus_f(float x) {
    return fmaxf(x, 0.f) + log1pf(expf(-fabsf(x)));
}
__device__ __forceinline__ float sigmoid_f(float x) {
    return 1.f / (1.f + expf(-x));
}

// ---------------- zero stats (graph replay safety) ----------------
__global__ void k_zero() {
    int t = threadIdx.x;
    if (t < 256) g_stats1[t] = 0.f;
    if (t < 128) g_stats2[t] = 0.f;
}

// ---------------- embedding: h = (atom_fea*mask) @ emb_W^T ; also emit masked x ----------------
__global__ void k_embed(const float* __restrict__ atom_fea,
                        const float* __restrict__ mask,
                        const float* __restrict__ embW,
                        float* __restrict__ out_masked) {
    __shared__ float s_x[64][93];    // [row][k]  (padded)
    __shared__ float s_WT[92][64];   // [k][o]
    int r0 = blockIdx.x * 64;
    int tid = threadIdx.x;           // 256
    int nrows = NATOM - r0; if (nrows > 64) nrows = 64;

    for (int i = tid; i < 92*64; i += 256) { int o = i / 92, k = i % 92; s_WT[k][o] = embW[i]; }
    for (int i = tid; i < nrows*92; i += 256) {
        int rr = i / 92, k = i % 92;
        float v = atom_fea[(size_t)(r0+rr)*92 + k] * mask[k];
        s_x[rr][k] = v;
        out_masked[(size_t)(r0+rr)*92 + k] = v;
    }
    __syncthreads();

    int ty = tid / 16, tx = tid % 16;   // rows ty*4.., cols tx*4..
    float acc[4][4] = {};
    for (int k = 0; k < 92; k++) {
        float b0 = s_WT[k][tx*4+0], b1 = s_WT[k][tx*4+1];
        float b2 = s_WT[k][tx*4+2], b3 = s_WT[k][tx*4+3];
        #pragma unroll
        for (int i = 0; i < 4; i++) {
            float a = s_x[ty*4+i][k];
            acc[i][0] += a*b0; acc[i][1] += a*b1; acc[i][2] += a*b2; acc[i][3] += a*b3;
        }
    }
    #pragma unroll
    for (int i = 0; i < 4; i++) {
        int r = r0 + ty*4 + i;
        if (r < NATOM) {
            #pragma unroll
            for (int j = 0; j < 4; j++) g_h[r*64 + tx*4 + j] = acc[i][j];
        }
    }
}

// ---------------- per-layer weight repack ----------------
__global__ void k_prepw(const float* __restrict__ W) {  // W: 128 x 169
    int i = blockIdx.x * 256 + threadIdx.x;
    if (i < 64*256) {
        int k = i / 256, o = i % 256;
        g_Wpre[i] = (o < 128) ? W[o*169 + k] : W[(o-128)*169 + 64 + k];
    } else if (i < 64*256 + 41*128) {
        int j = i - 64*256;
        int k = j / 128, o = j % 128;
        g_WfT[j] = W[o*169 + 128 + k];
    }
}

// ---------------- CH = h @ [Wc^T | Wn^T]  (N x 64) x (64 x 256) ----------------
__global__ void k_pre() {
    __shared__ float s_hT[64][68];   // [k][row]
    __shared__ float s_W[64][64];    // [k][col]
    int r0 = blockIdx.x * 64;
    int c0 = blockIdx.y * 64;
    int tid = threadIdx.x;           // 256
    int nrows = NATOM - r0; if (nrows > 64) nrows = 64;

    for (int i = tid; i < 64*64; i += 256) {
        int rr = i / 64, k = i % 64;
        s_hT[k][rr] = (rr < nrows) ? g_h[(size_t)(r0+rr)*64 + k] : 0.f;
    }
    for (int i = tid; i < 64*64; i += 256) {
        int k = i / 64, c = i % 64;
        s_W[k][c] = g_Wpre[k*256 + c0 + c];
    }
    __syncthreads();

    int ty = tid / 16, tx = tid % 16;
    float acc[4][4] = {};
    for (int k = 0; k < 64; k++) {
        float4 a = *(const float4*)&s_hT[k][ty*4];
        float4 b = *(const float4*)&s_W[k][tx*4];
        acc[0][0] += a.x*b.x; acc[0][1] += a.x*b.y; acc[0][2] += a.x*b.z; acc[0][3] += a.x*b.w;
        acc[1][0] += a.y*b.x; acc[1][1] += a.y*b.y; acc[1][2] += a.y*b.z; acc[1][3] += a.y*b.w;
        acc[2][0] += a.z*b.x; acc[2][1] += a.z*b.y; acc[2][2] += a.z*b.z; acc[2][3] += a.z*b.w;
        acc[3][0] += a.w*b.x; acc[3][1] += a.w*b.y; acc[3][2] += a.w*b.z; acc[3][3] += a.w*b.w;
    }
    #pragma unroll
    for (int i = 0; i < 4; i++) {
        int r = r0 + ty*4 + i;
        if (r < NATOM) {
            #pragma unroll
            for (int j = 0; j < 4; j++) g_CH[(size_t)r*256 + c0 + tx*4 + j] = acc[i][j];
        }
    }
}

// ---------------- main gemm: gated = C[n] + Hn[nbr] + nbr_fea@Wf^T + b ; fused BN1 stats ----------------
__global__ void k_conv_gemm(const float* __restrict__ nbr_fea,
                            const int*   __restrict__ nbr_idx,
                            const float* __restrict__ bias) {
    __shared__ float s_AT[41][68];    // [k][row]
    __shared__ float s_B[41][128];    // [k][col]
    __shared__ float s_sum[128], s_sq[128];
    __shared__ float s_bias[128];
    __shared__ int   s_nbr[64];
    __shared__ int   s_n[64];

    int r0 = blockIdx.x * 64;         // 9375 blocks, exact
    int tid = threadIdx.x;            // 256

    for (int i = tid; i < 64*41; i += 256) {
        int row = i / 41, k = i % 41;
        s_AT[k][row] = nbr_fea[(size_t)(r0+row)*41 + k];
    }
    for (int i = tid; i < 41*128; i += 256) s_B[i/128][i%128] = g_WfT[i];
    if (tid < 64) { int r = r0 + tid; s_nbr[tid] = nbr_idx[r]; s_n[tid] = r / 12; }
    if (tid < 128) { s_sum[tid] = 0.f; s_sq[tid] = 0.f; s_bias[tid] = bias[tid]; }
    __syncthreads();

    int ty = tid / 16, tx = tid % 16; // rows ty*4.., cols tx*8..
    float acc[4][8] = {};
    for (int k = 0; k < 41; k++) {
        float4 a  = *(const float4*)&s_AT[k][ty*4];
        float4 b0 = *(const float4*)&s_B[k][tx*8];
        float4 b1 = *(const float4*)&s_B[k][tx*8+4];
        float av[4] = {a.x, a.y, a.z, a.w};
        #pragma unroll
        for (int i = 0; i < 4; i++) {
            acc[i][0] += av[i]*b0.x; acc[i][1] += av[i]*b0.y;
            acc[i][2] += av[i]*b0.z; acc[i][3] += av[i]*b0.w;
            acc[i][4] += av[i]*b1.x; acc[i][5] += av[i]*b1.y;
            acc[i][6] += av[i]*b1.z; acc[i][7] += av[i]*b1.w;
        }
    }

    float cs[8] = {}, cq[8] = {};
    float bs[8];
    #pragma unroll
    for (int j = 0; j < 8; j++) bs[j] = s_bias[tx*8 + j];

    #pragma unroll
    for (int i = 0; i < 4; i++) {
        int lr = ty*4 + i;
        int n  = s_n[lr];
        int nb = s_nbr[lr];
        const float* cc = &g_CH[(size_t)n*256  + tx*8];
        const float* cn = &g_CH[(size_t)nb*256 + 128 + tx*8];
        float* go = &g_gated[(size_t)(r0+lr)*128 + tx*8];
        float v[8];
        #pragma unroll
        for (int j = 0; j < 8; j++) {
            v[j] = acc[i][j] + cc[j] + cn[j] + bs[j];
            cs[j] += v[j];
            cq[j] += v[j]*v[j];
        }
        *(float4*)&go[0] = make_float4(v[0], v[1], v[2], v[3]);
        *(float4*)&go[4] = make_float4(v[4], v[5], v[6], v[7]);
    }
    #pragma unroll
    for (int j = 0; j < 8; j++) {
        atomicAdd(&s_sum[tx*8+j], cs[j]);
        atomicAdd(&s_sq[tx*8+j], cq[j]);
    }
    __syncthreads();
    if (tid < 128) {
        atomicAdd(&g_stats1[tid],       s_sum[tid]);
        atomicAdd(&g_stats1[128 + tid], s_sq[tid]);
    }
}

// ---------------- BN1 params (also resets stats1) ----------------
__global__ void k_bn1(const float* __restrict__ g1, const float* __restrict__ b1) {
    int o = threadIdx.x; // 128
    float s = g_stats1[o], q = g_stats1[128+o];
    float inv = 1.f / (float)NM;
    float mu = s * inv;
    float var = q * inv - mu*mu;
    float a = g1[o] * rsqrtf(var + BN_EPS);
    g_bnp1[o] = a;
    g_bnp1[128+o] = b1[o] - mu*a;
    g_stats1[o] = 0.f;
    g_stats1[128+o] = 0.f;
}

// ---------------- apply BN1 + sigmoid*softplus + sum over M ; fused BN2 stats ----------------
__global__ void k_act() {
    __shared__ float s_s[64], s_q[64];
    int tid = threadIdx.x;         // 256 = 4 atoms x 64 features
    int j = tid & 63;
    int n = blockIdx.x*4 + (tid >> 6);
    if (tid < 64) { s_s[tid] = 0.f; s_q[tid] = 0.f; }
    __syncthreads();

    float af = g_bnp1[j],     cf = g_bnp1[128+j];
    float ac = g_bnp1[64+j],  cc = g_bnp1[192+j];
    const float* gp = &g_gated[(size_t)n*12*128];
    float sum = 0.f;
    #pragma unroll
    for (int m = 0; m < 12; m++) {
        float f = gp[m*128 + j];
        float c = gp[m*128 + 64 + j];
        sum += sigmoid_f(af*f + cf) * softplus_f(ac*c + cc);
    }
    g_summed[n*64 + j] = sum;
    atomicAdd(&s_s[j], sum);
    atomicAdd(&s_q[j], sum*sum);
    __syncthreads();
    if (tid < 64) {
        atomicAdd(&g_stats2[tid],      s_s[tid]);
        atomicAdd(&g_stats2[64 + tid], s_q[tid]);
    }
}

// ---------------- BN2 params (also resets stats2) ----------------
__global__ void k_bn2(const float* __restrict__ g2, const float* __restrict__ b2) {
    int o = threadIdx.x; // 64
    float s = g_stats2[o], q = g_stats2[64+o];
    float inv = 1.f / (float)NATOM;
    float mu = s * inv;
    float var = q * inv - mu*mu;
    float a = g2[o] * rsqrtf(var + BN_EPS);
    g_bnp2[o] = a;
    g_bnp2[64+o] = b2[o] - mu*a;
    g_stats2[o] = 0.f;
    g_stats2[64+o] = 0.f;
}

// ---------------- residual + softplus ----------------
__global__ void k_update() {
    int idx = blockIdx.x*256 + threadIdx.x;   // 12500 x 256 = N*64
    int j = idx & 63;
    float v = g_h[idx] + g_bnp2[j]*g_summed[idx] + g_bnp2[64+j];
    g_h[idx] = softplus_f(v);
}

// ---------------- per-atom inverse norm ----------------
__global__ void k_norm() {
    int tid = threadIdx.x;
    int warp = tid >> 5, lane = tid & 31;
    int n = blockIdx.x*8 + warp;              // 6250 x 8 = 50000
    float x0 = g_h[(size_t)n*64 + lane];
    float x1 = g_h[(size_t)n*64 + 32 + lane];
    float ss = x0*x0 + x1*x1;
    #pragma unroll
    for (int off = 16; off; off >>= 1) ss += __shfl_xor_sync(0xffffffffu, ss, off);
    if (lane == 0) g_inv[n] = 1.f / fmaxf(sqrtf(ss), 1e-12f);
}

// ---------------- crystal pooling ----------------
__global__ void k_pool(const int* __restrict__ cai) {
    int b = blockIdx.x, j = threadIdx.x;  // 500 x 64
    float s = 0.f;
    for (int a = 0; a < NACRY; a++) {
        int idx = cai[b*NACRY + a];
        s += g_h[(size_t)idx*64 + j] * g_inv[idx];
    }
    g_pooled[b*64 + j] = s * (1.f / (float)NACRY);
}

// ---------------- final MLP ----------------
__global__ void k_mlp(const float* __restrict__ fc1_W, const float* __restrict__ fc1_b,
                      const float* __restrict__ fc2_W, const float* __restrict__ fc2_b,
                      const float* __restrict__ out_W, const float* __restrict__ out_b,
                      float* __restrict__ props) {
    __shared__ float s_W[64*64];
    __shared__ float s_v[64];
    __shared__ float s_red[64];
    int b = blockIdx.x, j = threadIdx.x;  // 500 x 64

    s_v[j] = g_pooled[b*64 + j];
    for (int i = j; i < 4096; i += 64) s_W[i] = fc1_W[i];
    __syncthreads();
    float acc = fc1_b[j];
    for (int k = 0; k < 64; k++) acc += s_v[k] * s_W[j*64 + k];
    float z1 = softplus_f(acc);
    __syncthreads();
    s_v[j] = z1;
    for (int i = j; i < 4096; i += 64) s_W[i] = fc2_W[i];
    __syncthreads();
    acc = fc2_b[j];
    for (int k = 0; k < 64; k++) acc += s_v[k] * s_W[j*64 + k];
    float z2 = softplus_f(acc);
    s_red[j] = z2 * out_W[j];
    __syncthreads();
    for (int s = 32; s > 0; s >>= 1) {
        if (j < s) s_red[j] += s_red[j + s];
        __syncthreads();
    }
    if (j == 0) props[b] = s_red[0] + out_b[0];
}

// ---------------- launch ----------------
extern "C" void kernel_launch(void* const* d_in, const int* in_sizes, int n_in,
                              void* d_out, int out_size) {
    const float* atom_fea = (const float*)d_in[0];
    const float* nbr_fea  = (const float*)d_in[1];
    const int*   nbr_idx  = (const int*)d_in[2];
    const int*   cai      = (const int*)d_in[3];
    const float* mask     = (const float*)d_in[4];
    const float* emb_W    = (const float*)d_in[5];
    const float* conv_W   = (const float*)d_in[6];   // 3 x 128 x 169
    const float* conv_b   = (const float*)d_in[7];   // 3 x 128
    const float* bn1_g    = (const float*)d_in[8];
    const float* bn1_b    = (const float*)d_in[9];
    const float* bn2_g    = (const float*)d_in[10];
    const float* bn2_b    = (const float*)d_in[11];
    const float* fc1_W    = (const float*)d_in[12];
    const float* fc1_b    = (const float*)d_in[13];
    const float* fc2_W    = (const float*)d_in[14];
    const float* fc2_b    = (const float*)d_in[15];
    const float* out_W    = (const float*)d_in[16];
    const float* out_b    = (const float*)d_in[17];
    float* out = (float*)d_out;

    k_zero<<<1, 256>>>();
    k_embed<<<(NATOM + 63)/64, 256>>>(atom_fea, mask, emb_W, out + BCRY);

    for (int l = 0; l < NCONV; l++) {
        k_prepw<<<85, 256>>>(conv_W + (size_t)l*128*169);
        k_pre<<<dim3((NATOM + 63)/64, 4), 256>>>();
        k_conv_gemm<<<NM/64, 256>>>(nbr_fea, nbr_idx, conv_b + l*128);
        k_bn1<<<1, 128>>>(bn1_g + l*128, bn1_b + l*128);
        k_act<<<NATOM/4, 256>>>();
        k_bn2<<<1, 64>>>(bn2_g + l*64, bn2_b + l*64);
        k_update<<<NATOM*64/256, 256>>>();
    }

    k_norm<<<NATOM/8, 256>>>();
    k_pool<<<BCRY, 64>>>(cai);
    k_mlp<<<BCRY, 64>>>(fc1_W, fc1_b, fc2_W, fc2_b, out_W, out_b, out);
}

// round 2
// speedup vs baseline: 2.1819x; 2.1819x over previous
#include <cuda_runtime.h>
#include <cuda_bf16.h>
#include <math.h>
#include <stdint.h>

#define NATOM 50000
#define MNBR  12
#define AF    64
#define NBRF  41
#define ORIG  92
#define NCONV 3
#define NM    (NATOM*MNBR)
#define BCRY  500
#define NACRY 100
#define BN_EPS 1e-5f

// ---------------- scratch (static __device__, no allocation) ----------------
static __device__ float g_h[NATOM*AF];                    // fp32 atom features
static __device__ __nv_bfloat16 g_hbf[NATOM*AF];          // bf16 copy (GEMM input)
static __device__ __nv_bfloat16 g_CHb[NATOM*256];         // [0:128)=h@Wc^T, [128:256)=h@Wn^T (bf16)
static __device__ __nv_bfloat16 g_gatedb[(size_t)NM*128]; // 153.6 MB gated pre-activation (bf16)
static __device__ float g_summed[NATOM*AF];
static __device__ uint32_t g_BfC[3072];                   // conv Wf frags [s3][t16][lane32][r2]
static __device__ uint32_t g_BfP[8192];                   // pre  W frags [cy2][s4][t16][lane32][r2]
static __device__ float g_stats1[256];
static __device__ float g_stats2[128];
static __device__ float g_bnp1[256];
static __device__ float g_bnp2[128];
static __device__ float g_inv[NATOM];
static __device__ float g_pooled[BCRY*AF];

__device__ __forceinline__ float softplus_f(float x) {
    return fmaxf(x, 0.f) + log1pf(expf(-fabsf(x)));
}
__device__ __forceinline__ float sigmoid_f(float x) {
    return 1.f / (1.f + expf(-x));
}
__device__ __forceinline__ uint32_t packbf(float a, float b) {
    __nv_bfloat162 t = __floats2bfloat162_rn(a, b);  // .x = a (low)
    return *reinterpret_cast<uint32_t*>(&t);
}
__device__ __forceinline__ void mma16816(float d[4], const uint32_t a[4], uint32_t b0, uint32_t b1) {
    asm volatile(
        "mma.sync.aligned.m16n8k16.row.col.f32.bf16.bf16.f32 "
        "{%0,%1,%2,%3},{%4,%5,%6,%7},{%8,%9},{%0,%1,%2,%3};\n"
        : "+f"(d[0]), "+f"(d[1]), "+f"(d[2]), "+f"(d[3])
        : "r"(a[0]), "r"(a[1]), "r"(a[2]), "r"(a[3]), "r"(b0), "r"(b1));
}

// ---------------- zero stats ----------------
__global__ void k_zero() {
    int t = threadIdx.x;
    if (t < 256) g_stats1[t] = 0.f;
    if (t < 128) g_stats2[t] = 0.f;
}

// ---------------- embedding (SIMT fp32, one-shot) ----------------
__global__ void k_embed(const float* __restrict__ atom_fea,
                        const float* __restrict__ mask,
                        const float* __restrict__ embW,
                        float* __restrict__ out_masked) {
    __shared__ float s_x[64][93];
    __shared__ float s_WT[92][64];
    int r0 = blockIdx.x * 64;
    int tid = threadIdx.x;
    int nrows = NATOM - r0; if (nrows > 64) nrows = 64;

    for (int i = tid; i < 92*64; i += 256) { int o = i / 92, k = i % 92; s_WT[k][o] = embW[i]; }
    for (int i = tid; i < nrows*92; i += 256) {
        int rr = i / 92, k = i % 92;
        float v = atom_fea[(size_t)(r0+rr)*92 + k] * mask[k];
        s_x[rr][k] = v;
        out_masked[(size_t)(r0+rr)*92 + k] = v;
    }
    __syncthreads();

    int ty = tid / 16, tx = tid % 16;
    float acc[4][4] = {};
    for (int k = 0; k < 92; k++) {
        float b0 = s_WT[k][tx*4+0], b1 = s_WT[k][tx*4+1];
        float b2 = s_WT[k][tx*4+2], b3 = s_WT[k][tx*4+3];
        #pragma unroll
        for (int i = 0; i < 4; i++) {
            float a = s_x[ty*4+i][k];
            acc[i][0] += a*b0; acc[i][1] += a*b1; acc[i][2] += a*b2; acc[i][3] += a*b3;
        }
    }
    #pragma unroll
    for (int i = 0; i < 4; i++) {
        int r = r0 + ty*4 + i;
        if (r < NATOM) {
            #pragma unroll
            for (int j = 0; j < 4; j++) {
                g_h[r*64 + tx*4 + j] = acc[i][j];
                g_hbf[r*64 + tx*4 + j] = __float2bfloat16(acc[i][j]);
            }
        }
    }
}

// ---------------- per-layer weight -> mma B-fragments ----------------
// conv frag: idx = ((s*16+t)*32+lane)*2+r ; n = t*8+gid, k0 = s*16+2*tig+(r?8:0), Wf k<41
// pre  frag: idx2 = ((cy*4+s)*16+t)*32*2 ... ; n = cy*128+t*8+gid, k0<64
__global__ void k_prepw(const float* __restrict__ W) {  // W: 128 x 169
    int idx = blockIdx.x * 256 + threadIdx.x;
    if (idx < 3072) {
        int r = idx & 1, l = (idx >> 1) & 31, t = (idx >> 6) & 15, s = idx >> 10;
        int gid = l >> 2, tig = l & 3;
        int n = t*8 + gid;
        int k0 = s*16 + tig*2 + (r ? 8 : 0);
        float w0 = (k0   < 41) ? W[n*169 + 128 + k0]   : 0.f;
        float w1 = (k0+1 < 41) ? W[n*169 + 128 + k0+1] : 0.f;
        g_BfC[idx] = packbf(w0, w1);
    } else if (idx < 3072 + 8192) {
        int i2 = idx - 3072;
        int r = i2 & 1, l = (i2 >> 1) & 31, t = (i2 >> 6) & 15, s = (i2 >> 10) & 3, cy = i2 >> 12;
        int gid = l >> 2, tig = l & 3;
        int n = cy*128 + t*8 + gid;
        int k0 = s*16 + tig*2 + (r ? 8 : 0);
        float w0, w1;
        if (n < 128) { w0 = W[n*169 + k0]; w1 = W[n*169 + k0 + 1]; }
        else         { w0 = W[(n-128)*169 + 64 + k0]; w1 = W[(n-128)*169 + 64 + k0 + 1]; }
        g_BfP[i2] = packbf(w0, w1);
    }
}

// ---------------- CH = h @ [Wc^T | Wn^T] via bf16 mma ----------------
__global__ __launch_bounds__(256, 2) void k_pre_mma() {
    __shared__ __align__(16) unsigned char s_u[34816];
    __nv_bfloat16 (*s_A)[72] = (__nv_bfloat16(*)[72])s_u;      // 128 x 72 bf16 = 18432
    uint32_t* s_Bf = (uint32_t*)(s_u + 18432);                  // 4096 words = 16384
    __nv_bfloat16 (*s_D)[136] = (__nv_bfloat16(*)[136])s_u;     // 128 x 136 bf16 = 34816 (reuse)

    int r0 = blockIdx.x * 128;
    int cy = blockIdx.y;
    int tid = threadIdx.x;
    int nvalid = NATOM - r0; if (nvalid > 128) nvalid = 128;

    for (int i = tid; i < 4608; i += 256) ((uint32_t*)s_u)[i] = 0;   // zero A region
    __syncthreads();
    for (int i = tid; i < nvalid*32; i += 256) {
        int row = i >> 5, kk = i & 31;
        ((uint32_t*)s_u)[row*36 + kk] = ((const uint32_t*)g_hbf)[(size_t)(r0+row)*32 + kk];
    }
    for (int i = tid; i < 4096; i += 256) s_Bf[i] = g_BfP[cy*4096 + i];
    __syncthreads();

    int wid = tid >> 5, lane = tid & 31, gid = lane >> 2, tig = lane & 3;
    int wm = wid & 3, wn = wid >> 2;
    float acc[2][8][4];
    #pragma unroll
    for (int mt = 0; mt < 2; mt++)
        #pragma unroll
        for (int t = 0; t < 8; t++)
            #pragma unroll
            for (int j = 0; j < 4; j++) acc[mt][t][j] = 0.f;

    #pragma unroll
    for (int s = 0; s < 4; s++) {
        uint32_t a[2][4];
        #pragma unroll
        for (int mt = 0; mt < 2; mt++) {
            int row = wm*32 + mt*16 + gid;
            int kb = s*16 + 2*tig;
            a[mt][0] = *(const uint32_t*)&s_A[row][kb];
            a[mt][1] = *(const uint32_t*)&s_A[row+8][kb];
            a[mt][2] = *(const uint32_t*)&s_A[row][kb+8];
            a[mt][3] = *(const uint32_t*)&s_A[row+8][kb+8];
        }
        #pragma unroll
        for (int t = 0; t < 8; t++) {
            int gt = wn*8 + t;
            uint32_t b0 = s_Bf[((s*16+gt)*32+lane)*2];
            uint32_t b1 = s_Bf[((s*16+gt)*32+lane)*2 + 1];
            mma16816(acc[0][t], a[0], b0, b1);
            mma16816(acc[1][t], a[1], b0, b1);
        }
    }
    __syncthreads();
    #pragma unroll
    for (int mt = 0; mt < 2; mt++)
        #pragma unroll
        for (int t = 0; t < 8; t++) {
            int row = wm*32 + mt*16 + gid;
            int col = wn*64 + t*8 + 2*tig;
            *(uint32_t*)&s_D[row][col]   = packbf(acc[mt][t][0], acc[mt][t][1]);
            *(uint32_t*)&s_D[row+8][col] = packbf(acc[mt][t][2], acc[mt][t][3]);
        }
    __syncthreads();

    int ty = tid >> 4, tx = tid & 15;
    #pragma unroll
    for (int i = 0; i < 8; i++) {
        int r = ty*8 + i;
        if (r0 + r < NATOM)
            *(uint4*)&g_CHb[(size_t)(r0+r)*256 + cy*128 + tx*8] = *(const uint4*)&s_D[r][tx*8];
    }
}

// ---------------- main conv: nbr_fea@Wf^T (mma) + gathers + BN1 stats, bf16 gated out ----------------
__global__ __launch_bounds__(256, 2) void k_conv_mma(const float* __restrict__ nbr_fea,
                                                     const int*   __restrict__ nbr_idx,
                                                     const float* __restrict__ bias) {
    __shared__ __align__(16) unsigned char s_u[34816];
    __nv_bfloat16 (*s_A)[56] = (__nv_bfloat16(*)[56])s_u;      // 128 x 56 bf16 = 14336
    uint32_t* s_Bf = (uint32_t*)(s_u + 14336);                  // 3072 words = 12288
    __nv_bfloat16 (*s_D)[136] = (__nv_bfloat16(*)[136])s_u;     // reuse after mma
    __shared__ int   s_n[128], s_nbr[128];
    __shared__ float s_sum[128], s_sq[128], s_bias[128];

    int r0 = blockIdx.x * 128;
    int tid = threadIdx.x;
    int nvalid = NM - r0; if (nvalid > 128) nvalid = 128;

    for (int i = tid; i < 3584; i += 256) ((uint32_t*)s_u)[i] = 0;  // zero A
    __syncthreads();
    for (int i = tid; i < nvalid*41; i += 256)
        s_A[i/41][i%41] = __float2bfloat16(nbr_fea[(size_t)r0*41 + i]);
    for (int i = tid; i < 3072; i += 256) s_Bf[i] = g_BfC[i];
    if (tid < 128) {
        int e = r0 + tid;
        s_nbr[tid] = (e < NM) ? nbr_idx[e] : 0;
        s_n[tid]   = (e < NM) ? e / 12 : 0;
        s_sum[tid] = 0.f; s_sq[tid] = 0.f; s_bias[tid] = bias[tid];
    }
    __syncthreads();

    int wid = tid >> 5, lane = tid & 31, gid = lane >> 2, tig = lane & 3;
    int wm = wid & 3, wn = wid >> 2;
    float acc[2][8][4];
    #pragma unroll
    for (int mt = 0; mt < 2; mt++)
        #pragma unroll
        for (int t = 0; t < 8; t++)
            #pragma unroll
            for (int j = 0; j < 4; j++) acc[mt][t][j] = 0.f;

    #pragma unroll
    for (int s = 0; s < 3; s++) {
        uint32_t a[2][4];
        #pragma unroll
        for (int mt = 0; mt < 2; mt++) {
            int row = wm*32 + mt*16 + gid;
            int kb = s*16 + 2*tig;
            a[mt][0] = *(const uint32_t*)&s_A[row][kb];
            a[mt][1] = *(const uint32_t*)&s_A[row+8][kb];
            a[mt][2] = *(const uint32_t*)&s_A[row][kb+8];
            a[mt][3] = *(const uint32_t*)&s_A[row+8][kb+8];
        }
        #pragma unroll
        for (int t = 0; t < 8; t++) {
            int gt = wn*8 + t;
            uint32_t b0 = s_Bf[((s*16+gt)*32+lane)*2];
            uint32_t b1 = s_Bf[((s*16+gt)*32+lane)*2 + 1];
            mma16816(acc[0][t], a[0], b0, b1);
            mma16816(acc[1][t], a[1], b0, b1);
        }
    }
    __syncthreads();
    #pragma unroll
    for (int mt = 0; mt < 2; mt++)
        #pragma unroll
        for (int t = 0; t < 8; t++) {
            int row = wm*32 + mt*16 + gid;
            int col = wn*64 + t*8 + 2*tig;
            *(uint32_t*)&s_D[row][col]   = packbf(acc[mt][t][0], acc[mt][t][1]);
            *(uint32_t*)&s_D[row+8][col] = packbf(acc[mt][t][2], acc[mt][t][3]);
        }
    __syncthreads();

    // epilogue: 16x16 threads, each 8 rows x 8 cols
    int ty = tid >> 4, tx = tid & 15;
    float bs[8], cs[8], cq[8];
    #pragma unroll
    for (int j = 0; j < 8; j++) { bs[j] = s_bias[tx*8 + j]; cs[j] = 0.f; cq[j] = 0.f; }

    #pragma unroll
    for (int i = 0; i < 8; i++) {
        int lr = ty*8 + i;
        int e = r0 + lr;
        if (e < NM) {
            const __nv_bfloat162* cc = (const __nv_bfloat162*)&g_CHb[(size_t)s_n[lr]*256 + tx*8];
            const __nv_bfloat162* cn = (const __nv_bfloat162*)&g_CHb[(size_t)s_nbr[lr]*256 + 128 + tx*8];
            const __nv_bfloat162* dd = (const __nv_bfloat162*)&s_D[lr][tx*8];
            uint32_t o[4];
            #pragma unroll
            for (int jj = 0; jj < 4; jj++) {
                float2 d2 = __bfloat1622float2(dd[jj]);
                float2 c2 = __bfloat1622float2(cc[jj]);
                float2 n2 = __bfloat1622float2(cn[jj]);
                float v0 = d2.x + c2.x + n2.x + bs[2*jj];
                float v1 = d2.y + c2.y + n2.y + bs[2*jj+1];
                cs[2*jj]   += v0; cq[2*jj]   += v0*v0;
                cs[2*jj+1] += v1; cq[2*jj+1] += v1*v1;
                o[jj] = packbf(v0, v1);
            }
            *(uint4*)&g_gatedb[(size_t)e*128 + tx*8] = make_uint4(o[0], o[1], o[2], o[3]);
        }
    }
    #pragma unroll
    for (int j = 0; j < 8; j++) {
        atomicAdd(&s_sum[tx*8+j], cs[j]);
        atomicAdd(&s_sq[tx*8+j],  cq[j]);
    }
    __syncthreads();
    if (tid < 128) {
        atomicAdd(&g_stats1[tid],       s_sum[tid]);
        atomicAdd(&g_stats1[128 + tid], s_sq[tid]);
    }
}

// ---------------- BN1 params (resets stats1) ----------------
__global__ void k_bn1(const float* __restrict__ g1, const float* __restrict__ b1) {
    int o = threadIdx.x;
    float s = g_stats1[o], q = g_stats1[128+o];
    float inv = 1.f / (float)NM;
    float mu = s * inv;
    float var = q * inv - mu*mu;
    float a = g1[o] * rsqrtf(var + BN_EPS);
    g_bnp1[o] = a;
    g_bnp1[128+o] = b1[o] - mu*a;
    g_stats1[o] = 0.f;
    g_stats1[128+o] = 0.f;
}

// ---------------- BN1 apply + sigmoid*softplus + sum over M + BN2 stats ----------------
__global__ void k_act() {
    __shared__ float s_s[64], s_q[64];
    int tid = threadIdx.x;          // 256 = 8 atoms x 32 lanes
    int lane = tid & 31;
    int an = blockIdx.x*8 + (tid >> 5);
    if (tid < 64) { s_s[tid] = 0.f; s_q[tid] = 0.f; }
    __syncthreads();

    float2 af = *(const float2*)&g_bnp1[2*lane];
    float2 ac = *(const float2*)&g_bnp1[64 + 2*lane];
    float2 cf = *(const float2*)&g_bnp1[128 + 2*lane];
    float2 cc = *(const float2*)&g_bnp1[192 + 2*lane];
    const __nv_bfloat162* gp = (const __nv_bfloat162*)&g_gatedb[(size_t)an*1536];
    float sx = 0.f, sy = 0.f;
    #pragma unroll
    for (int m = 0; m < 12; m++) {
        float2 f = __bfloat1622float2(gp[m*64 + lane]);
        float2 c = __bfloat1622float2(gp[m*64 + 32 + lane]);
        sx += sigmoid_f(af.x*f.x + cf.x) * softplus_f(ac.x*c.x + cc.x);
        sy += sigmoid_f(af.y*f.y + cf.y) * softplus_f(ac.y*c.y + cc.y);
    }
    *(float2*)&g_summed[(size_t)an*64 + 2*lane] = make_float2(sx, sy);
    atomicAdd(&s_s[2*lane],   sx);
    atomicAdd(&s_s[2*lane+1], sy);
    atomicAdd(&s_q[2*lane],   sx*sx);
    atomicAdd(&s_q[2*lane+1], sy*sy);
    __syncthreads();
    if (tid < 64) {
        atomicAdd(&g_stats2[tid],      s_s[tid]);
        atomicAdd(&g_stats2[64 + tid], s_q[tid]);
    }
}

// ---------------- BN2 params (resets stats2) ----------------
__global__ void k_bn2(const float* __restrict__ g2, const float* __restrict__ b2) {
    int o = threadIdx.x;
    float s = g_stats2[o], q = g_stats2[64+o];
    float inv = 1.f / (float)NATOM;
    float mu = s * inv;
    float var = q * inv - mu*mu;
    float a = g2[o] * rsqrtf(var + BN_EPS);
    g_bnp2[o] = a;
    g_bnp2[64+o] = b2[o] - mu*a;
    g_stats2[o] = 0.f;
    g_stats2[64+o] = 0.f;
}

// ---------------- residual + softplus (fp32 + bf16 out) ----------------
__global__ void k_update() {
    int idx = blockIdx.x*256 + threadIdx.x;
    int j = idx & 63;
    float v = g_h[idx] + g_bnp2[j]*g_summed[idx] + g_bnp2[64+j];
    float r = softplus_f(v);
    g_h[idx] = r;
    g_hbf[idx] = __float2bfloat16(r);
}

// ---------------- per-atom inverse norm ----------------
__global__ void k_norm() {
    int tid = threadIdx.x;
    int warp = tid >> 5, lane = tid & 31;
    int n = blockIdx.x*8 + warp;
    float x0 = g_h[(size_t)n*64 + lane];
    float x1 = g_h[(size_t)n*64 + 32 + lane];
    float ss = x0*x0 + x1*x1;
    #pragma unroll
    for (int off = 16; off; off >>= 1) ss += __shfl_xor_sync(0xffffffffu, ss, off);
    if (lane == 0) g_inv[n] = 1.f / fmaxf(sqrtf(ss), 1e-12f);
}

// ---------------- crystal pooling ----------------
__global__ void k_pool(const int* __restrict__ cai) {
    int b = blockIdx.x, j = threadIdx.x;
    float s = 0.f;
    for (int a = 0; a < NACRY; a++) {
        int idx = cai[b*NACRY + a];
        s += g_h[(size_t)idx*64 + j] * g_inv[idx];
    }
    g_pooled[b*64 + j] = s * (1.f / (float)NACRY);
}

// ---------------- final MLP ----------------
__global__ void k_mlp(const float* __restrict__ fc1_W, const float* __restrict__ fc1_b,
                      const float* __restrict__ fc2_W, const float* __restrict__ fc2_b,
                      const float* __restrict__ out_W, const float* __restrict__ out_b,
                      float* __restrict__ props) {
    __shared__ float s_W[64*64];
    __shared__ float s_v[64];
    __shared__ float s_red[64];
    int b = blockIdx.x, j = threadIdx.x;

    s_v[j] = g_pooled[b*64 + j];
    for (int i = j; i < 4096; i += 64) s_W[i] = fc1_W[i];
    __syncthreads();
    float acc = fc1_b[j];
    for (int k = 0; k < 64; k++) acc += s_v[k] * s_W[j*64 + k];
    float z1 = softplus_f(acc);
    __syncthreads();
    s_v[j] = z1;
    for (int i = j; i < 4096; i += 64) s_W[i] = fc2_W[i];
    __syncthreads();
    acc = fc2_b[j];
    for (int k = 0; k < 64; k++) acc += s_v[k] * s_W[j*64 + k];
    float z2 = softplus_f(acc);
    s_red[j] = z2 * out_W[j];
    __syncthreads();
    for (int s = 32; s > 0; s >>= 1) {
        if (j < s) s_red[j] += s_red[j + s];
        __syncthreads();
    }
    if (j == 0) props[b] = s_red[0] + out_b[0];
}

// ---------------- launch ----------------
extern "C" void kernel_launch(void* const* d_in, const int* in_sizes, int n_in,
                              void* d_out, int out_size) {
    const float* atom_fea = (const float*)d_in[0];
    const float* nbr_fea  = (const float*)d_in[1];
    const int*   nbr_idx  = (const int*)d_in[2];
    const int*   cai      = (const int*)d_in[3];
    const float* mask     = (const float*)d_in[4];
    const float* emb_W    = (const float*)d_in[5];
    const float* conv_W   = (const float*)d_in[6];
    const float* conv_b   = (const float*)d_in[7];
    const float* bn1_g    = (const float*)d_in[8];
    const float* bn1_b    = (const float*)d_in[9];
    const float* bn2_g    = (const float*)d_in[10];
    const float* bn2_b    = (const float*)d_in[11];
    const float* fc1_W    = (const float*)d_in[12];
    const float* fc1_b    = (const float*)d_in[13];
    const float* fc2_W    = (const float*)d_in[14];
    const float* fc2_b    = (const float*)d_in[15];
    const float* out_W    = (const float*)d_in[16];
    const float* out_b    = (const float*)d_in[17];
    float* out = (float*)d_out;

    k_zero<<<1, 256>>>();
    k_embed<<<(NATOM + 63)/64, 256>>>(atom_fea, mask, emb_W, out + BCRY);

    for (int l = 0; l < NCONV; l++) {
        k_prepw<<<44, 256>>>(conv_W + (size_t)l*128*169);
        k_pre_mma<<<dim3((NATOM + 127)/128, 2), 256>>>();
        k_conv_mma<<<(NM + 127)/128, 256>>>(nbr_fea, nbr_idx, conv_b + l*128);
        k_bn1<<<1, 128>>>(bn1_g + l*128, bn1_b + l*128);
        k_act<<<NATOM/8, 256>>>();
        k_bn2<<<1, 64>>>(bn2_g + l*64, bn2_b + l*64);
        k_update<<<NATOM*64/256, 256>>>();
    }

    k_norm<<<NATOM/8, 256>>>();
    k_pool<<<BCRY, 64>>>(cai);
    k_mlp<<<BCRY, 64>>>(fc1_W, fc1_b, fc2_W, fc2_b, out_W, out_b, out);
}